// round 15
// baseline (speedup 1.0000x reference)
#include <cuda_runtime.h>
#include <math.h>

#define NMAX 8
#define LMMAX 16
#define N_SPECIES 4
#define NSEG 80000
#define CAP 32
#define OVF_CAP 4096

static constexpr float RC = 5.0f;
static constexpr float SMOOTH_W = 0.5f;
static constexpr float PI_F = 3.14159265358979323846f;
static constexpr float S_EXP = 1.69864363f;   // sqrt(2*log2(e))

// Static scratch: one float4 stream (R6/R11 layout).
__device__ int    d_cnt[NSEG + 1];          // [NSEG] = overflow counter
__device__ int    d_done;                   // last-block ticket
__device__ float4 d_bucket[NSEG * CAP];     // (r, x, y, z)
__device__ float4 d_ovf_data[OVF_CAP];
__device__ int    d_ovf_seg[OVF_CAP];

__device__ __forceinline__ float ex2(float a) {
    float y;
    asm("ex2.approx.ftz.f32 %0, %1;" : "=f"(y) : "f"(a));
    return y;
}

__device__ __forceinline__ float lg2(float a) {
    float y;
    asm("lg2.approx.ftz.f32 %0, %1;" : "=f"(y) : "f"(a));
    return y;
}

// log2(cutoff(r)): 0 for r<=4.5 (exact), -inf for r>=5 (ex2 -> 0, exact).
__device__ __forceinline__ float log2_cutoff(float r) {
    float t = __saturatef((r - (RC - SMOOTH_W)) * (1.0f / SMOOTH_W));
    return lg2(0.5f * (1.0f + __cosf(PI_F * t)));
}

__device__ __forceinline__ void sph_harm(float x, float y, float zd, float* Y) {
    float x2 = x * x, y2 = y * y, z2 = zd * zd;
    Y[0]  = 0.28209479177387814f;
    Y[1]  = 0.4886025119029199f * y;
    Y[2]  = 0.4886025119029199f * zd;
    Y[3]  = 0.4886025119029199f * x;
    Y[4]  = 1.0925484305920792f * x * y;
    Y[5]  = 1.0925484305920792f * y * zd;
    Y[6]  = 0.31539156525252005f * (2.0f * z2 - x2 - y2);
    Y[7]  = 1.0925484305920792f * x * zd;
    Y[8]  = 0.5462742152960396f * (x2 - y2);
    Y[9]  = 0.5900435899266435f * y * (3.0f * x2 - y2);
    Y[10] = 2.890611442640554f * x * y * zd;
    Y[11] = 0.4570457994644658f * y * (4.0f * z2 - x2 - y2);
    Y[12] = 0.3731763325901154f * zd * (2.0f * z2 - 3.0f * x2 - 3.0f * y2);
    Y[13] = 0.4570457994644658f * x * (4.0f * z2 - x2 - y2);
    Y[14] = 1.445305721320277f * zd * (x2 - y2);
    Y[15] = 0.5900435899266435f * x * (x2 - 3.0f * y2);
}

__global__ __launch_bounds__(256)
void fill_kernel(const float* __restrict__ dist,
                 const float* __restrict__ dirs,
                 const int* __restrict__ z,
                 const int* __restrict__ idx_i,
                 const int* __restrict__ idx_j,
                 int J)
{
    int e = blockIdx.x * blockDim.x + threadIdx.x;
    if (e >= J) return;
    float r  = __ldg(dist + e);
    float x  = __ldg(dirs + 3 * e + 0);
    float y  = __ldg(dirs + 3 * e + 1);
    float zd = __ldg(dirs + 3 * e + 2);
    int seg = __ldg(z + __ldg(idx_j + e)) + N_SPECIES * __ldg(idx_i + e);

    float4 v = make_float4(r, x, y, zd);
    int pos = atomicAdd(&d_cnt[seg], 1);
    if (pos < CAP) {
        d_bucket[seg * CAP + pos] = v;
    } else {
        int op = atomicAdd(&d_cnt[NSEG], 1);
        if (op < OVF_CAP) { d_ovf_data[op] = v; d_ovf_seg[op] = seg; }
    }
}

// One edge, two consecutive n values. R = 2^(lfc - t^2).
__device__ __forceinline__ void accum_edge(float r, float x, float y, float zd,
                                           float lfc,
                                           const float cs[4][2],
                                           float* __restrict__ acc0,
                                           float* __restrict__ acc1)
{
    float Ra[4], Rb[4];
#pragma unroll
    for (int l = 0; l < 4; l++) {
        float ta = fmaf(r, S_EXP, -cs[l][0]);
        float tb = fmaf(r, S_EXP, -cs[l][1]);
        Ra[l] = ex2(fmaf(-ta, ta, lfc));
        Rb[l] = ex2(fmaf(-tb, tb, lfc));
    }

    float Y[LMMAX];
    sph_harm(x, y, zd, Y);

    const int LTAB[LMMAX] = {0,1,1,1,2,2,2,2,2,3,3,3,3,3,3,3};
#pragma unroll
    for (int lm = 0; lm < LMMAX; lm++) {
        int l = LTAB[lm];
        acc0[lm] += Ra[l] * Y[lm];
        acc1[lm] += Rb[l] * Y[lm];
    }
}

// One thread per (segment, n-pair); direct sequential indexing (R11 structure).
// Self-cleans d_cnt; last block clears the overflow counter (no memset node).
__global__ __launch_bounds__(128)
void gather_kernel(const float* __restrict__ centers,
                   float* __restrict__ out)
{
    int tid = blockIdx.x * blockDim.x + threadIdx.x;
    if (tid >= NSEG * 4) return;
    int seg = tid >> 2;
    int np  = tid & 3;          // n0 = 2*np, n1 = 2*np+1

    float cs[4][2];             // S_EXP * center
#pragma unroll
    for (int l = 0; l < 4; l++) {
        cs[l][0] = S_EXP * __ldg(centers + l * NMAX + 2 * np + 0);
        cs[l][1] = S_EXP * __ldg(centers + l * NMAX + 2 * np + 1);
    }

    float acc0[LMMAX], acc1[LMMAX];
#pragma unroll
    for (int i = 0; i < LMMAX; i++) { acc0[i] = 0.0f; acc1[i] = 0.0f; }

    int cnt_raw = d_cnt[seg];
    int cnt = cnt_raw > CAP ? CAP : cnt_raw;
    const float4* bk = d_bucket + seg * CAP;

#pragma unroll 4
    for (int k = 0; k < cnt; k++) {
        float4 v = bk[k];
        // Warp-uniform MUFU skip: lfc == 0 exactly when every lane's r <= 4.5.
        float lfc = 0.0f;
        if (__any_sync(0xffffffffu, v.x > RC - SMOOTH_W))
            lfc = log2_cutoff(v.x);
        accum_edge(v.x, v.y, v.z, v.w, lfc, cs, acc0, acc1);
    }

    if (cnt_raw > CAP) {        // astronomically rare
        int novf = d_cnt[NSEG];
        if (novf > OVF_CAP) novf = OVF_CAP;
        for (int t2 = 0; t2 < novf; t2++) {
            if (d_ovf_seg[t2] == seg) {
                float4 v = d_ovf_data[t2];
                accum_edge(v.x, v.y, v.z, v.w, log2_cutoff(v.x), cs, acc0, acc1);
            }
        }
    }

    float4* o = (float4*)(out + (size_t)seg * (NMAX * LMMAX) + np * 2 * LMMAX);
    o[0] = make_float4(acc0[0],  acc0[1],  acc0[2],  acc0[3]);
    o[1] = make_float4(acc0[4],  acc0[5],  acc0[6],  acc0[7]);
    o[2] = make_float4(acc0[8],  acc0[9],  acc0[10], acc0[11]);
    o[3] = make_float4(acc0[12], acc0[13], acc0[14], acc0[15]);
    o[4] = make_float4(acc1[0],  acc1[1],  acc1[2],  acc1[3]);
    o[5] = make_float4(acc1[4],  acc1[5],  acc1[6],  acc1[7]);
    o[6] = make_float4(acc1[8],  acc1[9],  acc1[10], acc1[11]);
    o[7] = make_float4(acc1[12], acc1[13], acc1[14], acc1[15]);

    // Self-clean for the next graph replay (count already consumed above).
    if (np == 0) d_cnt[seg] = 0;

    if ((threadIdx.x == 0)) {
        __threadfence();
        int ticket = atomicAdd(&d_done, 1);
        if (ticket == (int)gridDim.x - 1) {
            d_cnt[NSEG] = 0;          // overflow counter
            d_done = 0;
        }
    }
}

extern "C" void kernel_launch(void* const* d_in, const int* in_sizes, int n_in,
                              void* d_out, int out_size) {
    const float* dist    = (const float*)d_in[0];
    const float* dirs    = (const float*)d_in[1];
    const float* centers = (const float*)d_in[2];
    const int*   z       = (const int*)d_in[3];
    const int*   idx_i   = (const int*)d_in[4];
    const int*   idx_j   = (const int*)d_in[5];
    float*       out     = (float*)d_out;

    int J = in_sizes[0];

    fill_kernel<<<(J + 255) / 256, 256>>>(dist, dirs, z, idx_i, idx_j, J);
    gather_kernel<<<(NSEG * 4 + 127) / 128, 128>>>(centers, out);
}

// round 16
// speedup vs baseline: 1.3194x; 1.3194x over previous
#include <cuda_runtime.h>
#include <math.h>

#define NMAX 8
#define LMMAX 16
#define N_SPECIES 4
#define NSEG 80000
#define CAP 32
#define OVF_CAP 4096

static constexpr float RC = 5.0f;
static constexpr float SMOOTH_W = 0.5f;
static constexpr float PI_F = 3.14159265358979323846f;
static constexpr float S_EXP = 1.69864363f;   // sqrt(2*log2(e))

// Static scratch: one float4 stream (R6/R11 layout).
__device__ int    d_cnt[NSEG + 1];          // [NSEG] = overflow counter
__device__ int    d_done;                   // last-block ticket
__device__ float4 d_bucket[NSEG * CAP];     // (r, x, y, z)
__device__ float4 d_ovf_data[OVF_CAP];
__device__ int    d_ovf_seg[OVF_CAP];

__device__ __forceinline__ float ex2(float a) {
    float y;
    asm("ex2.approx.ftz.f32 %0, %1;" : "=f"(y) : "f"(a));
    return y;
}

__device__ __forceinline__ float lg2(float a) {
    float y;
    asm("lg2.approx.ftz.f32 %0, %1;" : "=f"(y) : "f"(a));
    return y;
}

// log2(cutoff(r)): 0 for r<=4.5 (exact), -inf for r>=5 (ex2 -> 0, exact).
__device__ __forceinline__ float log2_cutoff(float r) {
    float t = __saturatef((r - (RC - SMOOTH_W)) * (1.0f / SMOOTH_W));
    return lg2(0.5f * (1.0f + __cosf(PI_F * t)));
}

__device__ __forceinline__ void sph_harm(float x, float y, float zd, float* Y) {
    float x2 = x * x, y2 = y * y, z2 = zd * zd;
    Y[0]  = 0.28209479177387814f;
    Y[1]  = 0.4886025119029199f * y;
    Y[2]  = 0.4886025119029199f * zd;
    Y[3]  = 0.4886025119029199f * x;
    Y[4]  = 1.0925484305920792f * x * y;
    Y[5]  = 1.0925484305920792f * y * zd;
    Y[6]  = 0.31539156525252005f * (2.0f * z2 - x2 - y2);
    Y[7]  = 1.0925484305920792f * x * zd;
    Y[8]  = 0.5462742152960396f * (x2 - y2);
    Y[9]  = 0.5900435899266435f * y * (3.0f * x2 - y2);
    Y[10] = 2.890611442640554f * x * y * zd;
    Y[11] = 0.4570457994644658f * y * (4.0f * z2 - x2 - y2);
    Y[12] = 0.3731763325901154f * zd * (2.0f * z2 - 3.0f * x2 - 3.0f * y2);
    Y[13] = 0.4570457994644658f * x * (4.0f * z2 - x2 - y2);
    Y[14] = 1.445305721320277f * zd * (x2 - y2);
    Y[15] = 0.5900435899266435f * x * (x2 - 3.0f * y2);
}

__global__ __launch_bounds__(256)
void fill_kernel(const float* __restrict__ dist,
                 const float* __restrict__ dirs,
                 const int* __restrict__ z,
                 const int* __restrict__ idx_i,
                 const int* __restrict__ idx_j,
                 int J)
{
    int e = blockIdx.x * blockDim.x + threadIdx.x;
    if (e >= J) return;
    float r  = __ldg(dist + e);
    float x  = __ldg(dirs + 3 * e + 0);
    float y  = __ldg(dirs + 3 * e + 1);
    float zd = __ldg(dirs + 3 * e + 2);
    int seg = __ldg(z + __ldg(idx_j + e)) + N_SPECIES * __ldg(idx_i + e);

    float4 v = make_float4(r, x, y, zd);
    int pos = atomicAdd(&d_cnt[seg], 1);
    if (pos < CAP) {
        d_bucket[seg * CAP + pos] = v;
    } else {
        int op = atomicAdd(&d_cnt[NSEG], 1);
        if (op < OVF_CAP) { d_ovf_data[op] = v; d_ovf_seg[op] = seg; }
    }
}

// One edge, two consecutive n values. R = 2^(lfc - t^2).
__device__ __forceinline__ void accum_edge(float r, float x, float y, float zd,
                                           const float cs[4][2],
                                           float* __restrict__ acc0,
                                           float* __restrict__ acc1)
{
    float lfc = log2_cutoff(r);   // per-thread, no warp-collective ops here

    float Ra[4], Rb[4];
#pragma unroll
    for (int l = 0; l < 4; l++) {
        float ta = fmaf(r, S_EXP, -cs[l][0]);
        float tb = fmaf(r, S_EXP, -cs[l][1]);
        Ra[l] = ex2(fmaf(-ta, ta, lfc));
        Rb[l] = ex2(fmaf(-tb, tb, lfc));
    }

    float Y[LMMAX];
    sph_harm(x, y, zd, Y);

    const int LTAB[LMMAX] = {0,1,1,1,2,2,2,2,2,3,3,3,3,3,3,3};
#pragma unroll
    for (int lm = 0; lm < LMMAX; lm++) {
        int l = LTAB[lm];
        acc0[lm] += Ra[l] * Y[lm];
        acc1[lm] += Rb[l] * Y[lm];
    }
}

// One thread per (segment, n-pair); direct sequential indexing (R11 structure).
// Self-cleans d_cnt; last block clears the overflow counter (no memset node).
__global__ __launch_bounds__(128)
void gather_kernel(const float* __restrict__ centers,
                   float* __restrict__ out)
{
    int tid = blockIdx.x * blockDim.x + threadIdx.x;
    if (tid >= NSEG * 4) return;
    int seg = tid >> 2;
    int np  = tid & 3;          // n0 = 2*np, n1 = 2*np+1

    float cs[4][2];             // S_EXP * center
#pragma unroll
    for (int l = 0; l < 4; l++) {
        cs[l][0] = S_EXP * __ldg(centers + l * NMAX + 2 * np + 0);
        cs[l][1] = S_EXP * __ldg(centers + l * NMAX + 2 * np + 1);
    }

    float acc0[LMMAX], acc1[LMMAX];
#pragma unroll
    for (int i = 0; i < LMMAX; i++) { acc0[i] = 0.0f; acc1[i] = 0.0f; }

    int cnt_raw = d_cnt[seg];
    int cnt = cnt_raw > CAP ? CAP : cnt_raw;
    const float4* bk = d_bucket + seg * CAP;

#pragma unroll 4
    for (int k = 0; k < cnt; k++) {
        float4 v = bk[k];
        accum_edge(v.x, v.y, v.z, v.w, cs, acc0, acc1);
    }

    if (cnt_raw > CAP) {        // astronomically rare
        int novf = d_cnt[NSEG];
        if (novf > OVF_CAP) novf = OVF_CAP;
        for (int t2 = 0; t2 < novf; t2++) {
            if (d_ovf_seg[t2] == seg) {
                float4 v = d_ovf_data[t2];
                accum_edge(v.x, v.y, v.z, v.w, cs, acc0, acc1);
            }
        }
    }

    float4* o = (float4*)(out + (size_t)seg * (NMAX * LMMAX) + np * 2 * LMMAX);
    o[0] = make_float4(acc0[0],  acc0[1],  acc0[2],  acc0[3]);
    o[1] = make_float4(acc0[4],  acc0[5],  acc0[6],  acc0[7]);
    o[2] = make_float4(acc0[8],  acc0[9],  acc0[10], acc0[11]);
    o[3] = make_float4(acc0[12], acc0[13], acc0[14], acc0[15]);
    o[4] = make_float4(acc1[0],  acc1[1],  acc1[2],  acc1[3]);
    o[5] = make_float4(acc1[4],  acc1[5],  acc1[6],  acc1[7]);
    o[6] = make_float4(acc1[8],  acc1[9],  acc1[10], acc1[11]);
    o[7] = make_float4(acc1[12], acc1[13], acc1[14], acc1[15]);

    // Self-clean for the next graph replay (count already consumed above).
    if (np == 0) d_cnt[seg] = 0;

    if (threadIdx.x == 0) {
        __threadfence();
        int ticket = atomicAdd(&d_done, 1);
        if (ticket == (int)gridDim.x - 1) {
            d_cnt[NSEG] = 0;          // overflow counter
            d_done = 0;
        }
    }
}

extern "C" void kernel_launch(void* const* d_in, const int* in_sizes, int n_in,
                              void* d_out, int out_size) {
    const float* dist    = (const float*)d_in[0];
    const float* dirs    = (const float*)d_in[1];
    const float* centers = (const float*)d_in[2];
    const int*   z       = (const int*)d_in[3];
    const int*   idx_i   = (const int*)d_in[4];
    const int*   idx_j   = (const int*)d_in[5];
    float*       out     = (float*)d_out;

    int J = in_sizes[0];

    fill_kernel<<<(J + 255) / 256, 256>>>(dist, dirs, z, idx_i, idx_j, J);
    gather_kernel<<<(NSEG * 4 + 127) / 128, 128>>>(centers, out);
}